// round 12
// baseline (speedup 1.0000x reference)
#include <cuda_runtime.h>
#include <cuda_fp16.h>
#include <cstdint>
#include <math.h>

#define B_ 4
#define S_ 2048
#define E_ 1024
#define H_ 16
#define D_ 64
#define M_ (B_*S_)   // 8192

// ---- scratch (static device allocations; runtime alloc is forbidden) ----
__device__ __half g_xh[(size_t)M_*E_];
__device__ __half g_Wq[(size_t)E_*E_];
__device__ __half g_Wk[(size_t)E_*E_];
__device__ __half g_Wo[(size_t)E_*E_];
__device__ __half g_Qh[(size_t)M_*E_];   // Q projection (fp16); also serves as V
__device__ __half g_Kh[(size_t)M_*E_];   // K projection (fp16)
__device__ __half g_Ah[(size_t)M_*E_];   // attention output (fp16)

// ============================ helpers ============================
__device__ __forceinline__ void cp16s(uint32_t dst, const void* src) {
    asm volatile("cp.async.cg.shared.global [%0], [%1], 16;" :: "r"(dst), "l"(src));
}
__device__ __forceinline__ void cp_commit() { asm volatile("cp.async.commit_group;"); }
__device__ __forceinline__ void cp_wait0()  { asm volatile("cp.async.wait_group 0;"); }
__device__ __forceinline__ void cp_wait1()  { asm volatile("cp.async.wait_group 1;"); }

__device__ __forceinline__ void mbar_init(uint32_t a, uint32_t n) {
    asm volatile("mbarrier.init.shared.b64 [%0], %1;" :: "r"(a), "r"(n) : "memory");
}
__device__ __forceinline__ void mbar_arrive(uint32_t a) {
    asm volatile("mbarrier.arrive.shared.b64 _, [%0];" :: "r"(a) : "memory");
}
__device__ __forceinline__ void cp_async_mbar_arrive_noinc(uint32_t a) {
    asm volatile("cp.async.mbarrier.arrive.noinc.shared::cta.b64 [%0];" :: "r"(a) : "memory");
}
__device__ __forceinline__ void mbar_wait(uint32_t a, uint32_t parity) {
    asm volatile(
        "{\n\t.reg .pred P;\n\t"
        "WAITLP_%=:\n\t"
        "mbarrier.try_wait.parity.acquire.cta.shared::cta.b64 P, [%0], %1, 0x989680;\n\t"
        "@P bra.uni WAITDN_%=;\n\t"
        "bra.uni WAITLP_%=;\n\t"
        "WAITDN_%=:\n\t}"
        :: "r"(a), "r"(parity) : "memory");
}

__device__ __forceinline__ void ldsm4(uint32_t& r0, uint32_t& r1, uint32_t& r2, uint32_t& r3,
                                      uint32_t addr) {
    asm volatile("ldmatrix.sync.aligned.m8n8.x4.shared.b16 {%0,%1,%2,%3}, [%4];"
                 : "=r"(r0), "=r"(r1), "=r"(r2), "=r"(r3) : "r"(addr));
}
__device__ __forceinline__ void ldsm4t(uint32_t& r0, uint32_t& r1, uint32_t& r2, uint32_t& r3,
                                       uint32_t addr) {
    asm volatile("ldmatrix.sync.aligned.m8n8.x4.trans.shared.b16 {%0,%1,%2,%3}, [%4];"
                 : "=r"(r0), "=r"(r1), "=r"(r2), "=r"(r3) : "r"(addr));
}
// mma m16n8k16 fp16 in, fp32 accum (baseline ISA)
__device__ __forceinline__ void mma16816(float* c, uint32_t a0, uint32_t a1, uint32_t a2,
                                         uint32_t a3, uint32_t b0, uint32_t b1) {
    asm volatile(
        "mma.sync.aligned.m16n8k16.row.col.f32.f16.f16.f32 "
        "{%0,%1,%2,%3},{%4,%5,%6,%7},{%8,%9},{%0,%1,%2,%3};"
        : "+f"(c[0]), "+f"(c[1]), "+f"(c[2]), "+f"(c[3])
        : "r"(a0), "r"(a1), "r"(a2), "r"(a3), "r"(b0), "r"(b1));
}
__device__ __forceinline__ uint32_t h2u(__half2 h) { return *(uint32_t*)&h; }
__device__ __forceinline__ uint32_t h2exp2(uint32_t x) {
    uint32_t r;
    asm volatile("ex2.approx.f16x2 %0, %1;" : "=r"(r) : "r"(x));
    return r;
}

// ============================================================================
// fp32 -> fp16 convert, ALL tensors in one launch
// ============================================================================
__global__ void f2h_all_kernel(const float* __restrict__ x,  const float* __restrict__ Wq,
                               const float* __restrict__ Wk, const float* __restrict__ Wo,
                               __half* __restrict__ xh, __half* __restrict__ wq,
                               __half* __restrict__ wk, __half* __restrict__ wo)
{
    const int NX = (M_ * E_) / 4;
    const int NW = (E_ * E_) / 4;
    int i = blockIdx.x * blockDim.x + threadIdx.x;
    const float* in;
    __half* out;
    int off;
    if (i < NX) { in = x; out = xh; off = i; }
    else {
        int j = i - NX;
        int seg = j / NW, r = j - seg * NW;
        in  = (seg == 0) ? Wq : (seg == 1) ? Wk : Wo;
        out = (seg == 0) ? wq : (seg == 1) ? wk : wo;
        off = r;
    }
    float4 v = ((const float4*)in)[off];
    ((__half2*)out)[2*off]     = __floats2half2_rn(v.x, v.y);
    ((__half2*)out)[2*off + 1] = __floats2half2_rn(v.z, v.w);
}

// ============================================================================
// fp16 tensor-core NT GEMM, WARP TILE 64x64 (was 64x32).
// CTA tile 128(M) x 256(N), 8 warps 2(M)x4(N), acc = 128 fp32/thread.
// Per ks: 8 LDSM.x4 feed 32 HMMAs (ratio 4:1) -> smem crossbar demand drops
// below the tensor-pipe wall (both were ~balanced at 53% before).
// 3-stage cp.async pipeline (48KB/stage = A 16KB + B 32KB), 1 sync/k-tile.
// DUAL=1: blockIdx.x&1 selects (W,C) vs (W2,C2).
// ============================================================================
#define GA_BYTES 16384              // A: 128 x 64 halves
#define GB_BYTES 32768              // B: 256 x 64 halves
#define GSTG_BYTES (GA_BYTES + GB_BYTES)
#define GEMM_SMEM (3 * GSTG_BYTES)  // 144KB

template<int BIAS, int DUAL>
__global__ void __launch_bounds__(256, 1)
gemm_h_kernel(const __half* __restrict__ A, const __half* __restrict__ W,
              const float* __restrict__ bias, void* __restrict__ Cout,
              const __half* __restrict__ W2, void* __restrict__ Cout2,
              int M, int N, int K)
{
    extern __shared__ __half smh[];
    const uint32_t uS = (uint32_t)__cvta_generic_to_shared(smh);

    const int tid = threadIdx.x;
    const int wid = tid >> 5, lane = tid & 31;
    const int g = lane >> 2, tig = lane & 3;
    const int wm = wid & 1, wn = wid >> 1;      // 2(M) x 4(N) warps
    const int row0 = blockIdx.y * 128;
    int col0;
    const __half* Wm;
    void* Cm;
    if (DUAL) {
        col0 = ((int)blockIdx.x >> 1) * 256;
        if (blockIdx.x & 1) { Wm = W2; Cm = Cout2; }
        else                { Wm = W;  Cm = Cout;  }
    } else {
        col0 = blockIdx.x * 256;
        Wm = W; Cm = Cout;
    }

    float acc[4][8][4];
    #pragma unroll
    for (int mi = 0; mi < 4; mi++)
        #pragma unroll
        for (int ni = 0; ni < 8; ni++)
            #pragma unroll
            for (int r = 0; r < 4; r++) acc[mi][ni][r] = 0.f;

    auto tload = [&](int kt, int st) {
        const uint32_t base = uS + st * GSTG_BYTES;
        #pragma unroll
        for (int j = 0; j < 4; j++) {           // A: 1024 chunks
            const int idx = tid + 256 * j;
            const int r = idx >> 3, c = idx & 7;
            const uint32_t off = (r * 64 + ((c ^ (r & 7)) << 3)) * 2;
            cp16s(base + off, A + (size_t)(row0 + r) * K + kt * 64 + c * 8);
        }
        #pragma unroll
        for (int j = 0; j < 8; j++) {           // B: 2048 chunks
            const int idx = tid + 256 * j;
            const int r = idx >> 3, c = idx & 7;
            const uint32_t off = (r * 64 + ((c ^ (r & 7)) << 3)) * 2;
            cp16s(base + GA_BYTES + off, Wm + (size_t)(col0 + r) * K + kt * 64 + c * 8);
        }
    };

    tload(0, 0); cp_commit();
    tload(1, 1); cp_commit();

    const int NT = K >> 6;
    int st = 0;
    for (int kt = 0; kt < NT; kt++) {
        if (kt + 1 < NT) cp_wait1(); else cp_wait0();
        __syncthreads();
        if (kt + 2 < NT) {
            int sp = st + 2; if (sp >= 3) sp -= 3;
            tload(kt + 2, sp); cp_commit();
        }

        const uint32_t bA = uS + st * GSTG_BYTES;
        const uint32_t bB = bA + GA_BYTES;
        #pragma unroll
        for (int ks = 0; ks < 4; ks++) {
            // B fragments: 64 cols of this warp's slab = 4 ldsm4 -> 8 n-blocks
            uint32_t bb[8][2];
            #pragma unroll
            for (int p = 0; p < 4; p++) {
                const int rowb = wn * 64 + p * 16 + (lane & 7) + ((lane >= 16) ? 8 : 0);
                const int ch   = 2 * ks + ((lane >> 3) & 1);
                const uint32_t ad = bB + (rowb * 64 + ((ch ^ (rowb & 7)) << 3)) * 2;
                ldsm4(bb[2*p][0], bb[2*p][1], bb[2*p+1][0], bb[2*p+1][1], ad);
            }
            #pragma unroll
            for (int mi = 0; mi < 4; mi++) {
                const int rowa = wm * 64 + mi * 16 + (lane & 7) + (((lane >> 3) & 1) ? 8 : 0);
                const int ch   = 2 * ks + ((lane >> 4) & 1);
                const uint32_t ad = bA + (rowa * 64 + ((ch ^ (rowa & 7)) << 3)) * 2;
                uint32_t a0, a1, a2, a3;
                ldsm4(a0, a1, a2, a3, ad);
                #pragma unroll
                for (int ni = 0; ni < 8; ni++)
                    mma16816(acc[mi][ni], a0, a1, a2, a3, bb[ni][0], bb[ni][1]);
            }
        }
        if (++st == 3) st = 0;
    }

    #pragma unroll
    for (int mi = 0; mi < 4; mi++) {
        const int r = row0 + wm * 64 + mi * 16 + g;
        #pragma unroll
        for (int ni = 0; ni < 8; ni++) {
            const int c = col0 + wn * 64 + ni * 8 + 2 * tig;
            if (BIAS) {
                float* C = (float*)Cm;
                const float b0 = bias[c], b1 = bias[c + 1];
                *(float2*)(C + (size_t)r * N + c)       = make_float2(acc[mi][ni][0] + b0, acc[mi][ni][1] + b1);
                *(float2*)(C + (size_t)(r + 8) * N + c) = make_float2(acc[mi][ni][2] + b0, acc[mi][ni][3] + b1);
            } else {
                __half* C = (__half*)Cm;
                *(__half2*)(C + (size_t)r * N + c)       = __floats2half2_rn(acc[mi][ni][0], acc[mi][ni][1]);
                *(__half2*)(C + (size_t)(r + 8) * N + c) = __floats2half2_rn(acc[mi][ni][2], acc[mi][ni][3]);
            }
        }
    }
}

// ============================================================================
// fp16 tensor-core causal flash attention (UNCHANGED from R11 — verified).
// V = Q (faithful to reference bug). 4 warps x 32 q-rows, mbarrier pipeline.
// ============================================================================
#define AT_STG 4
#define AT_TILE 16384
#define ATTN_SMEM (AT_STG * AT_TILE)

__global__ void __launch_bounds__(128, 2)
attn_h_kernel(const __half* __restrict__ Qh, const __half* __restrict__ Kh,
              __half* __restrict__ Oh)
{
    extern __shared__ __half dynsm[];
    __shared__ uint64_t mbars[8];

    const uint32_t uS = (uint32_t)__cvta_generic_to_shared(dynsm);
    const uint32_t uMF = (uint32_t)__cvta_generic_to_shared(&mbars[0]);
    const uint32_t uME = uMF + 32;

    const int qt = 15 - (int)blockIdx.x;
    const int h  = blockIdx.y;
    const int b  = blockIdx.z;
    const int tid = threadIdx.x;
    const int wid = tid >> 5, lane = tid & 31;
    const int g = lane >> 2, tig = lane & 3;
    const int rbase = qt * 128 + wid * 32 + g;

    if (tid == 0) {
        #pragma unroll
        for (int s = 0; s < 4; s++) {
            mbar_init(uMF + 8 * s, 32);
            mbar_init(uME + 8 * s, 128);
        }
    }
    __syncthreads();

    size_t gr[2][2];
    #pragma unroll
    for (int mb = 0; mb < 2; mb++) {
        gr[mb][0] = (size_t)(b * S_ + rbase + mb * 16) * E_ + h * 64;
        gr[mb][1] = gr[mb][0] + (size_t)8 * E_;
    }

    uint32_t qa[2][4][4];
    #pragma unroll
    for (int mb = 0; mb < 2; mb++)
        #pragma unroll
        for (int ks = 0; ks < 4; ks++) {
            const int c0 = 16 * ks + 2 * tig;
            qa[mb][ks][0] = *(const uint32_t*)(Qh + gr[mb][0] + c0);
            qa[mb][ks][1] = *(const uint32_t*)(Qh + gr[mb][1] + c0);
            qa[mb][ks][2] = *(const uint32_t*)(Qh + gr[mb][0] + c0 + 8);
            qa[mb][ks][3] = *(const uint32_t*)(Qh + gr[mb][1] + c0 + 8);
        }

    float of[2][8][4];
    #pragma unroll
    for (int mb = 0; mb < 2; mb++)
        #pragma unroll
        for (int nj = 0; nj < 8; nj++)
            #pragma unroll
            for (int r = 0; r < 4; r++) of[mb][nj][r] = 0.f;
    float lsum[2][2] = {{0.f, 0.f}, {0.f, 0.f}};

    const int nkt = 2 * qt + 2;

    auto produce = [&](int kt) {
        const int s = kt & 3;
        const int r = kt >> 2;
        if (r > 0) mbar_wait(uME + 8 * s, (uint32_t)((r - 1) & 1));
        const uint32_t base = uS + s * AT_TILE;
        #pragma unroll
        for (int j = 0; j < 16; j++) {
            const int idx = lane + 32 * j;
            const int rr = idx >> 3, cc = idx & 7;
            const uint32_t off = (rr * 64 + ((cc ^ (rr & 7)) << 3)) * 2;
            const size_t gsrc = (size_t)(b * S_ + kt * 64 + rr) * E_ + h * 64 + cc * 8;
            cp16s(base + off,        Kh + gsrc);
            cp16s(base + 8192 + off, Qh + gsrc);   // V = Q
        }
        cp_async_mbar_arrive_noinc(uMF + 8 * s);
    };

    #pragma unroll
    for (int kp = 0; kp < 3; kp++)
        if (kp < nkt && (kp & 3) == wid) produce(kp);

    for (int kt = 0; kt < nkt; kt++) {
        {
            const int kp = kt + 3;
            if (kp < nkt && (kp & 3) == wid) produce(kp);
        }
        const int s = kt & 3;
        mbar_wait(uMF + 8 * s, (uint32_t)((kt >> 2) & 1));

        const uint32_t bK = uS + s * AT_TILE;
        const uint32_t bV = bK + 8192;

        float sf[2][8][4];
        #pragma unroll
        for (int mb = 0; mb < 2; mb++)
            #pragma unroll
            for (int ni = 0; ni < 8; ni++)
                #pragma unroll
                for (int r = 0; r < 4; r++) sf[mb][ni][r] = 0.f;

        #pragma unroll
        for (int ks = 0; ks < 4; ks++) {
            uint32_t bb[8][2];
            #pragma unroll
            for (int p = 0; p < 4; p++) {
                const int rowb = p * 16 + (lane & 7) + ((lane >= 16) ? 8 : 0);
                const int ch   = 2 * ks + ((lane >> 3) & 1);
                const uint32_t ad = bK + (rowb * 64 + ((ch ^ (rowb & 7)) << 3)) * 2;
                ldsm4(bb[2*p][0], bb[2*p][1], bb[2*p+1][0], bb[2*p+1][1], ad);
            }
            #pragma unroll
            for (int ni = 0; ni < 8; ni++) {
                mma16816(sf[0][ni], qa[0][ks][0], qa[0][ks][1], qa[0][ks][2], qa[0][ks][3],
                         bb[ni][0], bb[ni][1]);
                mma16816(sf[1][ni], qa[1][ks][0], qa[1][ks][1], qa[1][ks][2], qa[1][ks][3],
                         bb[ni][0], bb[ni][1]);
            }
        }

        const float FS = 0.03125f * 1.44269504f;
        uint32_t ph[2][2][8];
        if (kt >= 2 * qt) {
            const int k0 = kt * 64;
            #pragma unroll
            for (int mb = 0; mb < 2; mb++) {
                const int rq = rbase + mb * 16;
                __half2 ls0 = __floats2half2_rn(0.f, 0.f), ls1 = ls0;
                #pragma unroll
                for (int ni = 0; ni < 8; ni++) {
                    const int kc = k0 + ni * 8 + 2 * tig;
                    float t0 = (kc     <= rq)     ? sf[mb][ni][0] * FS : -100.f;
                    float t1 = (kc + 1 <= rq)     ? sf[mb][ni][1] * FS : -100.f;
                    float t2 = (kc     <= rq + 8) ? sf[mb][ni][2] * FS : -100.f;
                    float t3 = (kc + 1 <= rq + 8) ? sf[mb][ni][3] * FS : -100.f;
                    ph[mb][0][ni] = h2exp2(h2u(__floats2half2_rn(t0, t1)));
                    ph[mb][1][ni] = h2exp2(h2u(__floats2half2_rn(t2, t3)));
                    ls0 = __hadd2(ls0, *(__half2*)&ph[mb][0][ni]);
                    ls1 = __hadd2(ls1, *(__half2*)&ph[mb][1][ni]);
                }
                float2 f0 = __half22float2(ls0);
                float2 f1 = __half22float2(ls1);
                lsum[mb][0] += f0.x + f0.y;
                lsum[mb][1] += f1.x + f1.y;
            }
        } else {
            #pragma unroll
            for (int mb = 0; mb < 2; mb++) {
                __half2 ls0 = __floats2half2_rn(0.f, 0.f), ls1 = ls0;
                #pragma unroll
                for (int ni = 0; ni < 8; ni++) {
                    ph[mb][0][ni] = h2exp2(h2u(__floats2half2_rn(sf[mb][ni][0] * FS, sf[mb][ni][1] * FS)));
                    ph[mb][1][ni] = h2exp2(h2u(__floats2half2_rn(sf[mb][ni][2] * FS, sf[mb][ni][3] * FS)));
                    ls0 = __hadd2(ls0, *(__half2*)&ph[mb][0][ni]);
                    ls1 = __hadd2(ls1, *(__half2*)&ph[mb][1][ni]);
                }
                float2 f0 = __half22float2(ls0);
                float2 f1 = __half22float2(ls1);
                lsum[mb][0] += f0.x + f0.y;
                lsum[mb][1] += f1.x + f1.y;
            }
        }

        #pragma unroll
        for (int ks = 0; ks < 4; ks++) {
            uint32_t bb[8][2];
            #pragma unroll
            for (int p = 0; p < 4; p++) {
                const int rowb = 16 * ks + (lane & 7) + (((lane >> 3) & 1) ? 8 : 0);
                const int ch   = 2 * p + ((lane >= 16) ? 1 : 0);
                const uint32_t ad = bV + (rowb * 64 + ((ch ^ (rowb & 7)) << 3)) * 2;
                ldsm4t(bb[2*p][0], bb[2*p][1], bb[2*p+1][0], bb[2*p+1][1], ad);
            }
            #pragma unroll
            for (int nj = 0; nj < 8; nj++) {
                mma16816(of[0][nj], ph[0][0][2*ks], ph[0][1][2*ks],
                         ph[0][0][2*ks+1], ph[0][1][2*ks+1], bb[nj][0], bb[nj][1]);
                mma16816(of[1][nj], ph[1][0][2*ks], ph[1][1][2*ks],
                         ph[1][0][2*ks+1], ph[1][1][2*ks+1], bb[nj][0], bb[nj][1]);
            }
        }

        mbar_arrive(uME + 8 * s);
    }

    #pragma unroll
    for (int mb = 0; mb < 2; mb++) {
        float l0 = lsum[mb][0], l1 = lsum[mb][1];
        l0 += __shfl_xor_sync(0xffffffffu, l0, 1);
        l0 += __shfl_xor_sync(0xffffffffu, l0, 2);
        l1 += __shfl_xor_sync(0xffffffffu, l1, 1);
        l1 += __shfl_xor_sync(0xffffffffu, l1, 2);
        const float i0 = 1.f / l0, i1 = 1.f / l1;
        #pragma unroll
        for (int nj = 0; nj < 8; nj++) {
            const int c = nj * 8 + 2 * tig;
            *(__half2*)(Oh + gr[mb][0] + c) = __floats2half2_rn(of[mb][nj][0] * i0, of[mb][nj][1] * i0);
            *(__half2*)(Oh + gr[mb][1] + c) = __floats2half2_rn(of[mb][nj][2] * i1, of[mb][nj][3] * i1);
        }
    }
}

// ============================================================================
// launch
// ============================================================================
extern "C" void kernel_launch(void* const* d_in, const int* in_sizes, int n_in,
                              void* d_out, int out_size)
{
    (void)in_sizes; (void)n_in; (void)out_size;
    const float* x  = (const float*)d_in[0];
    const float* Wk = (const float*)d_in[1];
    const float* Wq = (const float*)d_in[2];
    // d_in[3] = Wv — computed-then-discarded in the reference; skipped.
    const float* Wo = (const float*)d_in[4];
    const float* bo = (const float*)d_in[5];
    float* out = (float*)d_out;

    __half *xh, *wq, *wk, *wo, *Qp, *Kp, *Ap;
    cudaGetSymbolAddress((void**)&xh, g_xh);
    cudaGetSymbolAddress((void**)&wq, g_Wq);
    cudaGetSymbolAddress((void**)&wk, g_Wk);
    cudaGetSymbolAddress((void**)&wo, g_Wo);
    cudaGetSymbolAddress((void**)&Qp, g_Qh);
    cudaGetSymbolAddress((void**)&Kp, g_Kh);
    cudaGetSymbolAddress((void**)&Ap, g_Ah);

    cudaFuncSetAttribute(gemm_h_kernel<0,1>, cudaFuncAttributeMaxDynamicSharedMemorySize, GEMM_SMEM);
    cudaFuncSetAttribute(gemm_h_kernel<1,0>, cudaFuncAttributeMaxDynamicSharedMemorySize, GEMM_SMEM);
    cudaFuncSetAttribute(attn_h_kernel,      cudaFuncAttributeMaxDynamicSharedMemorySize, ATTN_SMEM);

    const int NTOT = (M_ * E_ + 3 * E_ * E_) / 4;
    f2h_all_kernel<<<NTOT / 256, 256>>>(x, Wq, Wk, Wo, xh, wq, wk, wo);

    // fused Q+K projections: blockIdx.x&1 selects weight/output (CTA 128x256)
    dim3 qkGrid(2 * E_ / 256, M_ / 128);   // (8, 64)
    gemm_h_kernel<0,1><<<qkGrid, 256, GEMM_SMEM>>>(xh, wq, nullptr, Qp, wk, Kp, M_, E_, E_);

    dim3 aGrid(S_ / 128, H_, B_);          // (16, 16, 4)
    attn_h_kernel<<<aGrid, 128, ATTN_SMEM>>>(Qp, Kp, Ap);

    dim3 oGrid(E_ / 256, M_ / 128);        // (4, 64)
    gemm_h_kernel<1,0><<<oGrid, 256, GEMM_SMEM>>>(Ap, wo, bo, out, nullptr, nullptr, M_, E_, E_);
}